// round 10
// baseline (speedup 1.0000x reference)
#include <cuda_runtime.h>
#include <math.h>

#define NMODES 6400
#define MMAX 80
#define GROUPS 25          // NMODES / 256
#define GSZ 256
#define SCHUNK 64          // samples per plate block
#define SH 32              // SCHUNK/2 packed f32x2 accumulators
#define NCB 1024           // bucket table size (chunks); N=44100 -> 690 chunks
#define SEGС 32
#define SEGS 32            // chunks per seed-walker segment (NCB/32 segments max)

typedef unsigned long long u64;

// ---------------- static device scratch (no runtime allocation) -------------
__device__ float4 gA0[NMODES], gB0[NMODES];   // staging (mode-index order)
__device__ float4 gA[NMODES],  gB[NMODES];    // sorted by lifetime desc
__device__ float2 gC2[NMODES];                // sorted (a2, -b2) for plate
__device__ int    gLcS[NMODES];               // sorted live-chunk counts
__device__ int    gLc[NMODES];                // live-chunk count per mode
__device__ int    gRank[NMODES];              // deterministic rank in (group,bucket)
__device__ int    gH[GROUPS][NCB];            // per-group bucket histograms
__device__ int    gGOff[GROUPS][NCB];         // cross-group prefix per bucket
__device__ int    gBase[NCB];                 // live count L(c)
__device__ int    gRow[NCB];                  // seed row offset R(c)=sum_{c'<c}L(c')
__device__ float4 gSeed[NMODES * NCB];        // per-(chunk,mode) seeds (ragged rows)
__device__ unsigned int gPeakBits;

// ---------------- f32x2 packed helpers (Blackwell FFMA2 path) ---------------
__device__ __forceinline__ u64 pack2(float lo, float hi) {
    u64 r; asm("mov.b64 %0, {%1, %2};" : "=l"(r) : "f"(lo), "f"(hi)); return r;
}
__device__ __forceinline__ u64 fma2(u64 a, u64 b, u64 c) {
    u64 d; asm("fma.rn.f32x2 %0, %1, %2, %3;" : "=l"(d) : "l"(a), "l"(b), "l"(c)); return d;
}
__device__ __forceinline__ u64 mul2(u64 a, u64 b) {
    u64 d; asm("mul.rn.f32x2 %0, %1, %2;" : "=l"(d) : "l"(a), "l"(b)); return d;
}
__device__ __forceinline__ u64 add2(u64 a, u64 b) {
    u64 d; asm("add.rn.f32x2 %0, %1, %2;" : "=l"(d) : "l"(a), "l"(b)); return d;
}

__device__ __forceinline__ float softplusf(float x) {
    return (x > 20.0f) ? x : log1pf(expf(x));
}

// ---------------------------------------------------------------------------
// S1: per-mode precompute (fp32) + per-group histogram + deterministic rank.
// grid = 25 x 256.
// ---------------------------------------------------------------------------
__global__ void __launch_bounds__(GSZ) s1_kernel(
    const float* __restrict__ pmu, const float* __restrict__ pD,
    const float* __restrict__ pT0, const float* __restrict__ pLy,
    const float* __restrict__ pxo, const float* __restrict__ pyo, int NC)
{
    const int g = blockIdx.x, t = threadIdx.x;
    const int i = g * GSZ + t;
    const int warp = t >> 5, lane = t & 31;

    if (g == 0 && t == 0) gPeakBits = 0u;

    float mu   = softplusf(pmu[0]) + 1e-4f;
    float Dmu  = softplusf(pD[0])  + 1e-4f;
    float T0mu = softplusf(pT0[0]) + 1e-4f;
    float Ly = 1.1f + (4.0f - 1.1f) * ((tanhf(pLy[0]) + 1.0f) * 0.5f);
    const float LX = 0.5f;
    float xo = 0.49f * LX + (1.0f - 0.49f) * LX * ((tanhf(pxo[0]) + 1.0f) * 0.5f);
    float yo = 0.51f * Ly + (1.0f - 0.51f) * Ly * ((tanhf(pyo[0]) + 1.0f) * 0.5f);

    const float PI  = 3.14159265358979323846f;
    const float Kf  = (float)(1.0 / 44100.0);
    const float MAXOM = (float)(10000.0 * 2.0 * 3.141592653589793);
    const float MINOM = (float)(20.0 * 2.0 * 3.141592653589793);
    const double OM2   = 2.0 * 3.141592653589793 * 500.0;
    const double DOMSQ = OM2 * OM2;
    const double LN10T3 = 3.0 * 2.302585092994045684;
    const float ALPHA = (float)(LN10T3 / DOMSQ * (DOMSQ / 6.0));
    const float BETA  = (float)(LN10T3 / DOMSQ * (1.0 / 1.0 - 1.0 / 6.0));

    float m  = (float)(i / MMAX + 1);
    float nn = (float)(i % MMAX + 1);

    // omega / validity path identical (fp32) to the known-passing kernel
    float t1 = (m * PI) / LX;
    float t2 = (nn * PI) / Ly;
    float g1 = t1 * t1 + t2 * t2;
    float w2 = T0mu * g1 + (Dmu * g1) * g1;
    w2 = fmaxf(w2, 0.0f);
    float omega = sqrtf(w2);
    int valid = (omega <= MAXOM) && (omega >= MINOM);

    float sigma = ALPHA + BETA * (omega * omega);
    float xi = 0.1f * LX, yi = 0.1f * Ly;
    float in_w  = cosf(((xi * PI) * m) / LX) * cosf(((yi * PI) * nn) / Ly);
    float out_w = cosf(((xo * PI) * m) / LX) * cosf(((yo * PI) * nn) / Ly);
    float ms = 0.25f * mu * LX * Ly;
    float P  = out_w * in_w * (Kf * Kf) * expf(-sigma * Kf) / ms;

    float thK  = omega * Kf;
    float sigK = sigma * Kf;

    float sth, cth;
    sincosf(thK, &sth, &cth);
    float r   = expf(-sigK);
    float r2  = r * r;
    float c2  = fmaf(-2.0f * sth, sth, 1.0f);   // cos(2*thK) = 1 - 2 sin^2
    float a2  = 2.0f * r2 * c2;
    float nb2 = -(r2 * r2);
    float C   = P / (sth + 1e-8f);

    float cutoff = 20.0f / sigK;                // live while sigK*(n-1) <= 20
    int lc = 0;
    if (valid) {
        lc = (int)floorf((cutoff + 1.0f) / 64.0f) + 1;
        lc = max(0, min(lc, min(NC, NCB - 1)));
    }

    gA0[i] = make_float4(a2, nb2, C, r);        // .w = e^{-sigK}
    gB0[i] = make_float4(thK, sth, cth, sigK);
    gLc[i] = lc;

    // deterministic rank within (group,bucket): match-any within warp,
    // fixed warp order across warps
    __shared__ int sh_h[NCB];
    for (int b = t; b < NCB; b += GSZ) sh_h[b] = 0;
    __syncthreads();

    unsigned msk = __match_any_sync(0xFFFFFFFFu, lc);
    int riw    = __popc(msk & ((1u << lane) - 1u));
    int leader = __ffs(msk) - 1;
    int cnt    = __popc(msk);
    int rk = 0;
    #pragma unroll
    for (int w = 0; w < 8; ++w) {
        if (warp == w) {
            int base = 0;
            if (lane == leader) base = atomicAdd(&sh_h[lc], cnt);
            base = __shfl_sync(0xFFFFFFFFu, base, leader);
            rk = base + riw;
        }
        __syncthreads();
    }
    gRank[i] = rk;
    for (int b = t; b < NCB; b += GSZ) gH[g][b] = sh_h[b];
}

// ---------------------------------------------------------------------------
// S2: one block x 1024. Group-prefix table, suffix scan -> gBase (=L(c)),
// then forward prefix scan of L -> gRow (seed row offsets).
// ---------------------------------------------------------------------------
__global__ void __launch_bounds__(1024) s2_kernel(int NC)
{
    __shared__ int incl[NCB];
    __shared__ int orig[NCB];
    __shared__ int lsh[NCB];
    const int t = threadIdx.x;
    const int NB = min(NC, NCB - 1);            // max bucket index
    const int b = NB - t;                       // reversed mapping

    int s = 0;
    if (b >= 0) {
        #pragma unroll
        for (int g = 0; g < GROUPS; ++g) {
            gGOff[g][b] = s;                    // prefix over earlier groups
            s += gH[g][b];
        }
    }
    incl[t] = s; orig[t] = s;
    __syncthreads();

    for (int off = 1; off < NCB; off <<= 1) {
        int v = (t >= off) ? incl[t - off] : 0;
        __syncthreads();
        incl[t] += v;
        __syncthreads();
    }
    if (b >= 0) {
        int Lval = incl[t] - orig[t];           // strict suffix sum = L(b)
        gBase[b] = Lval;
        lsh[b] = Lval;
    }
    __syncthreads();

    // forward exclusive prefix of L over chunk index -> gRow
    int v0 = (t <= NB) ? lsh[t] : 0;
    incl[t] = v0; orig[t] = v0;
    __syncthreads();
    for (int off = 1; off < NCB; off <<= 1) {
        int v = (t >= off) ? incl[t - off] : 0;
        __syncthreads();
        incl[t] += v;
        __syncthreads();
    }
    if (t <= NB) gRow[t] = incl[t] - orig[t];
}

// ---------------------------------------------------------------------------
// S3: scatter to lifetime-descending order.  grid = 25 x 256.
// ---------------------------------------------------------------------------
__global__ void __launch_bounds__(GSZ) s3_kernel()
{
    const int g = blockIdx.x, t = threadIdx.x;
    const int i = g * GSZ + t;
    int lc = gLc[i];
    int pos = gBase[lc] + gGOff[g][lc] + gRank[i];
    float4 A = gA0[i];
    gA[pos]  = A;
    gB[pos]  = gB0[i];
    gC2[pos] = make_float2(A.x, A.y);
    gLcS[pos] = lc;
}

// ---------------------------------------------------------------------------
// Seed walker: one thread per (sorted mode, 32-chunk segment). Anchors with
// sincosf/__expf once, then rotates phase by 64*theta and envelope by r^64
// per chunk, storing seed float4 (y(n0-2), y(n0-1), y(n0), y(n0+1)).
// Mode i's slot in row c is i (sorted prefix property) -> coalesced.
// grid = NMODES*SEGS/256 = 800 x 256.
// ---------------------------------------------------------------------------
__global__ void __launch_bounds__(256) seed_kernel()
{
    int f = blockIdx.x * 256 + threadIdx.x;
    int sseg = f / NMODES;                      // 0..SEGS-1
    int i    = f - sseg * NMODES;
    int lc = gLcS[i];
    int c0 = sseg * SEGS;
    if (c0 >= lc) return;
    int c1 = min(c0 + SEGS, lc);

    float4 A = gA[i];                           // {a2, -b2, C, r}
    float4 B = gB[i];                           // {thK, sth, cth, sigK}
    float C_ = A.z, r = A.w;
    float rinv  = __frcp_rn(r);
    float rinv2 = rinv * rinv;
    float sth = B.y, cth = B.z;

    float n0s = (float)(c0 * SCHUNK);
    float s, c;
    sincosf(n0s * B.x, &s, &c);                 // anchor (accurate)
    float E = __expf(-B.w * (n0s - 1.0f));
    float s64, c64;
    sincosf(64.0f * B.x, &s64, &c64);
    float r64 = __expf(-64.0f * B.w);

    for (int cc = c0; cc < c1; ++cc) {
        float sp1 = fmaf(s, cth,  c * sth);     // sin((n0+1)θ)
        float sm1 = fmaf(s, cth, -c * sth);     // sin((n0-1)θ)
        float sm2 = fmaf(2.0f * cth, sm1, -s);  // sin((n0-2)θ)
        float CE  = C_ * E;
        gSeed[gRow[cc] + i] = make_float4(CE * rinv2 * sm2, CE * rinv * sm1,
                                          CE * s,           CE * r * sp1);
        float sn = fmaf(s, c64,  c * s64);      // rotate by 64θ
        float cn = fmaf(c, c64, -s * s64);
        s = sn; c = cn;
        E *= r64;
    }
}

// ---------------------------------------------------------------------------
// Plate: one block per 64-sample chunk. Mode loop = 2 loads + pure 31-step
// packed recurrence per mode (2 independent chains for FMA-latency ILP).
// ---------------------------------------------------------------------------
__global__ void __launch_bounds__(256, 2) plate_kernel(float* __restrict__ out, int N)
{
    const int lane = threadIdx.x & 31;
    const int warp = threadIdx.x >> 5;
    const int c    = blockIdx.x;
    const int n0   = c * SCHUNK;
    const int Lc   = gBase[c];                  // live modes = sorted prefix
    const int row  = gRow[c];

    const ulonglong2* __restrict__ seeds = (const ulonglong2*)gSeed;

    u64 acc[SH];
    #pragma unroll
    for (int j = 0; j < SH; ++j) acc[j] = 0ull;

    #pragma unroll 1
    for (int i = threadIdx.x; i < Lc; i += 512) {
        int idx1 = i + 256;
        bool on2 = idx1 < Lc;
        int i2 = on2 ? idx1 : i;

        float2 K1 = gC2[i];
        float2 K2 = gC2[i2];
        ulonglong2 S1 = seeds[row + i];         // .x = (y-2,y-1), .y = (y0,y1)
        ulonglong2 S2 = seeds[row + i2];

        u64 vp1 = S1.x, vc1 = S1.y;
        u64 vp2 = on2 ? S2.x : 0ull;
        u64 vc2 = on2 ? S2.y : 0ull;
        u64 A21  = pack2(K1.x, K1.x), nB21 = pack2(K1.y, K1.y);
        u64 A22  = pack2(K2.x, K2.x), nB22 = pack2(K2.y, K2.y);

        acc[0] = add2(acc[0], add2(vc1, vc2));
        #pragma unroll
        for (int j = 1; j < SH; ++j) {
            u64 m1 = mul2(nB21, vp1);
            u64 m2 = mul2(nB22, vp2);
            u64 n1 = fma2(A21, vc1, m1);
            u64 n2 = fma2(A22, vc2, m2);
            vp1 = vc1; vc1 = n1;
            vp2 = vc2; vc2 = n2;
            acc[j] = add2(acc[j], add2(n1, n2));
        }
    }

    // warp transpose-reduce: lane l ends owning sample pair (2l, 2l+1)
    #pragma unroll
    for (int stage = 0; stage < 5; ++stage) {
        const int d = 16 >> stage;
        const bool hi = (lane & d) != 0;
        #pragma unroll
        for (int j = 0; j < (16 >> stage); ++j) {
            const int mm = 16 >> stage;
            u64 a_ = acc[j], b_ = acc[j + mm];
            u64 send = hi ? a_ : b_;
            u64 keep = hi ? b_ : a_;
            u64 recv = __shfl_xor_sync(0xFFFFFFFFu, send, d);
            acc[j] = add2(keep, recv);
        }
    }

    __shared__ u64 sred[8][33];
    sred[warp][lane] = acc[0];
    __syncthreads();

    if (threadIdx.x < SCHUNK) {
        const int j = threadIdx.x;
        const float* f = (const float*)sred;    // row stride = 66 floats
        float v = 0.0f;
        #pragma unroll
        for (int w = 0; w < 8; ++w) v += f[w * 66 + j];

        int sample = n0 + j;
        float av = fabsf(v);
        if (sample < N) out[sample] = v; else av = 0.0f;
        #pragma unroll
        for (int o = 16; o > 0; o >>= 1)
            av = fmaxf(av, __shfl_xor_sync(0xFFFFFFFFu, av, o));
        if (lane == 0) atomicMax(&gPeakBits, __float_as_uint(av));
    }
}

// ---------------------------------------------------------------------------
__global__ void scale_kernel(float* __restrict__ out, int N)
{
    int i = blockIdx.x * blockDim.x + threadIdx.x;
    if (i < N) {
        float peak = __uint_as_float(gPeakBits) + 1e-8f;
        out[i] = out[i] / peak;
    }
}

// ---------------------------------------------------------------------------
extern "C" void kernel_launch(void* const* d_in, const int* in_sizes, int n_in,
                              void* d_out, int out_size)
{
    const float* mu  = (const float*)d_in[0];
    const float* Dm  = (const float*)d_in[1];
    const float* T0m = (const float*)d_in[2];
    const float* Lyr = (const float*)d_in[3];
    const float* xr  = (const float*)d_in[4];
    const float* yr  = (const float*)d_in[5];
    int N  = out_size;                          // == num_samples
    int NC = (N + SCHUNK - 1) / SCHUNK;
    float* out = (float*)d_out;

    s1_kernel<<<GROUPS, GSZ>>>(mu, Dm, T0m, Lyr, xr, yr, NC);
    s2_kernel<<<1, 1024>>>(NC);
    s3_kernel<<<GROUPS, GSZ>>>();
    seed_kernel<<<(NMODES * SEGS) / 256, 256>>>();
    plate_kernel<<<NC, 256>>>(out, N);
    scale_kernel<<<(N + 255) / 256, 256>>>(out, N);
}

// round 11
// speedup vs baseline: 1.4917x; 1.4917x over previous
#include <cuda_runtime.h>
#include <math.h>

#define NMODES 6400
#define MMAX 80
#define GROUPS 25          // NMODES / 256 (s1 grid)
#define GSZ 256
#define SCHUNK 64          // samples per chunk
#define SH 32              // SCHUNK/2 packed f32x2 accumulators
#define PBLK 296           // persistent plate blocks = 2/SM * 148 (co-resident)

typedef unsigned long long u64;

// ---------------- static device scratch (no runtime allocation) -------------
__device__ float4 gA[NMODES];        // {a2, -b2, C, r=e^{-sigK}}
__device__ float4 gB[NMODES];        // {thK, sth, cth, sigK (NaN if invalid)}
__device__ unsigned int gPeakBits;
__device__ int gSync;                // barrier arrival counter (reset by s1)
__device__ volatile int gFlag;       // barrier release flag   (reset by s1)

// ---------------- f32x2 packed helpers (Blackwell FFMA2 path) ---------------
__device__ __forceinline__ u64 pack2(float lo, float hi) {
    u64 r; asm("mov.b64 %0, {%1, %2};" : "=l"(r) : "f"(lo), "f"(hi)); return r;
}
__device__ __forceinline__ u64 fma2(u64 a, u64 b, u64 c) {
    u64 d; asm("fma.rn.f32x2 %0, %1, %2, %3;" : "=l"(d) : "l"(a), "l"(b), "l"(c)); return d;
}
__device__ __forceinline__ u64 mul2(u64 a, u64 b) {
    u64 d; asm("mul.rn.f32x2 %0, %1, %2;" : "=l"(d) : "l"(a), "l"(b)); return d;
}
__device__ __forceinline__ u64 add2(u64 a, u64 b) {
    u64 d; asm("add.rn.f32x2 %0, %1, %2;" : "=l"(d) : "l"(a), "l"(b)); return d;
}

__device__ __forceinline__ float softplusf(float x) {
    return (x > 20.0f) ? x : log1pf(expf(x));
}

// ---------------------------------------------------------------------------
// S1: per-mode precompute only (fp32, mode-index order). grid = 25 x 256.
// Also resets peak + barrier state for this replay (runs before plate).
// ---------------------------------------------------------------------------
__global__ void __launch_bounds__(GSZ) s1_kernel(
    const float* __restrict__ pmu, const float* __restrict__ pD,
    const float* __restrict__ pT0, const float* __restrict__ pLy,
    const float* __restrict__ pxo, const float* __restrict__ pyo)
{
    const int i = blockIdx.x * GSZ + threadIdx.x;
    if (i == 0) { gPeakBits = 0u; gSync = 0; gFlag = 0; }

    float mu   = softplusf(pmu[0]) + 1e-4f;
    float Dmu  = softplusf(pD[0])  + 1e-4f;
    float T0mu = softplusf(pT0[0]) + 1e-4f;
    float Ly = 1.1f + (4.0f - 1.1f) * ((tanhf(pLy[0]) + 1.0f) * 0.5f);
    const float LX = 0.5f;
    float xo = 0.49f * LX + (1.0f - 0.49f) * LX * ((tanhf(pxo[0]) + 1.0f) * 0.5f);
    float yo = 0.51f * Ly + (1.0f - 0.51f) * Ly * ((tanhf(pyo[0]) + 1.0f) * 0.5f);

    const float PI  = 3.14159265358979323846f;
    const float Kf  = (float)(1.0 / 44100.0);
    const float MAXOM = (float)(10000.0 * 2.0 * 3.141592653589793);
    const float MINOM = (float)(20.0 * 2.0 * 3.141592653589793);
    const double OM2   = 2.0 * 3.141592653589793 * 500.0;
    const double DOMSQ = OM2 * OM2;
    const double LN10T3 = 3.0 * 2.302585092994045684;
    const float ALPHA = (float)(LN10T3 / DOMSQ * (DOMSQ / 6.0));
    const float BETA  = (float)(LN10T3 / DOMSQ * (1.0 / 1.0 - 1.0 / 6.0));

    float m  = (float)(i / MMAX + 1);
    float nn = (float)(i % MMAX + 1);

    // omega / validity path identical (fp32) to the known-passing kernel
    float t1 = (m * PI) / LX;
    float t2 = (nn * PI) / Ly;
    float g1 = t1 * t1 + t2 * t2;
    float w2 = T0mu * g1 + (Dmu * g1) * g1;
    w2 = fmaxf(w2, 0.0f);
    float omega = sqrtf(w2);
    int valid = (omega <= MAXOM) && (omega >= MINOM);

    float sigma = ALPHA + BETA * (omega * omega);
    float xi = 0.1f * LX, yi = 0.1f * Ly;
    float in_w  = cosf(((xi * PI) * m) / LX) * cosf(((yi * PI) * nn) / Ly);
    float out_w = cosf(((xo * PI) * m) / LX) * cosf(((yo * PI) * nn) / Ly);
    float ms = 0.25f * mu * LX * Ly;
    float P  = out_w * in_w * (Kf * Kf) * expf(-sigma * Kf) / ms;

    float thK  = omega * Kf;
    float sigK = sigma * Kf;

    float sth, cth;
    sincosf(thK, &sth, &cth);
    float r   = expf(-sigK);
    float r2  = r * r;
    float c2  = fmaf(-2.0f * sth, sth, 1.0f);   // cos(2*thK) = 1 - 2 sin^2
    float a2  = 2.0f * r2 * c2;
    float nb2 = -(r2 * r2);
    float C   = P / (sth + 1e-8f);

    // invalid modes: sigK := NaN so (n0m1 * sigK <= 20) is ALWAYS false
    float sigKst = valid ? sigK : __int_as_float(0x7FC00000);

    gA[i] = make_float4(a2, nb2, C, r);
    gB[i] = make_float4(thK, sth, cth, sigKst);
}

// ---------------------------------------------------------------------------
// Persistent plate: 296 co-resident blocks grid-stride over 64-sample chunks
// (R4 2-chain body, warp-coherent liveness skip), then grid barrier, then
// normalize phase inline.  Saves two kernel launches.
// ---------------------------------------------------------------------------
struct Chain { u64 vc, vp, A2, nB2; };

__device__ __forceinline__ Chain seed_chain(float4 A, float4 B,
                                            float n0f, float n0m1, bool on)
{
    float s0, c0;
    sincosf(n0f * B.x, &s0, &c0);               // accurate phase re-seed
    float E0   = __expf(-B.w * n0m1);
    float r    = A.w;                           // e^{-sigK} precomputed
    float rinv = __frcp_rn(r);

    float sp1 = fmaf(s0, B.z,  c0 * B.y);       // sin((n0+1)θ)
    float sm1 = fmaf(s0, B.z, -c0 * B.y);       // sin((n0-1)θ)
    float sm2 = fmaf(2.0f * B.z, sm1, -s0);     // sin((n0-2)θ)

    float CE = on ? (A.z * E0) : 0.0f;          // SEL: NaN-safe when off
    Chain ch;
    ch.vc  = pack2(CE * s0, CE * r * sp1);                     // y(n0), y(n0+1)
    ch.vp  = pack2(CE * (rinv * rinv) * sm2, CE * rinv * sm1); // y(n0-2), y(n0-1)
    ch.A2  = pack2(A.x, A.x);
    ch.nB2 = pack2(A.y, A.y);
    return ch;
}

__global__ void __launch_bounds__(256, 2) plate_kernel(float* __restrict__ out, int N, int NC)
{
    const int lane = threadIdx.x & 31;
    const int warp = threadIdx.x >> 5;
    __shared__ u64 sred[8][33];

    for (int c = blockIdx.x; c < NC; c += gridDim.x) {
        const int n0 = c * SCHUNK;
        const float n0f  = (float)n0;
        const float n0m1 = n0f - 1.0f;

        u64 acc[SH];
        #pragma unroll
        for (int j = 0; j < SH; ++j) acc[j] = 0ull;

        #pragma unroll 1
        for (int i = threadIdx.x; i < NMODES; i += 512) {
            int ib = i + 256;
            bool in2 = ib < NMODES;
            int i2 = in2 ? ib : i;

            float4 B1 = gB[i];
            float4 B2 = gB[i2];
            // liveness: n0m1*sigK <= 20 (false for NaN-encoded invalid modes)
            bool on1 = (n0m1 * B1.w <= 20.0f);
            bool on2 = in2 && (n0m1 * B2.w <= 20.0f);
            if (!on1 && !on2) continue;          // warp-coherent (smooth omega)

            float4 A1 = gA[i];
            float4 A2_ = gA[i2];
            Chain ca = seed_chain(A1, B1, n0f, n0m1, on1);
            Chain cb = seed_chain(A2_, B2, n0f, n0m1, on2);

            acc[0] = add2(acc[0], add2(ca.vc, cb.vc));
            #pragma unroll
            for (int j = 1; j < SH; ++j) {
                u64 ma = mul2(ca.nB2, ca.vp);
                u64 mb = mul2(cb.nB2, cb.vp);
                u64 na = fma2(ca.A2, ca.vc, ma);
                u64 nb = fma2(cb.A2, cb.vc, mb);
                ca.vp = ca.vc; ca.vc = na;
                cb.vp = cb.vc; cb.vc = nb;
                acc[j] = add2(acc[j], add2(na, nb));
            }
        }

        // warp transpose-reduce: lane l ends owning sample pair (2l, 2l+1)
        #pragma unroll
        for (int stage = 0; stage < 5; ++stage) {
            const int d = 16 >> stage;
            const bool hi = (lane & d) != 0;
            #pragma unroll
            for (int j = 0; j < (16 >> stage); ++j) {
                const int mm = 16 >> stage;
                u64 a_ = acc[j], b_ = acc[j + mm];
                u64 send = hi ? a_ : b_;
                u64 keep = hi ? b_ : a_;
                u64 recv = __shfl_xor_sync(0xFFFFFFFFu, send, d);
                acc[j] = add2(keep, recv);
            }
        }

        sred[warp][lane] = acc[0];
        __syncthreads();

        if (threadIdx.x < SCHUNK) {
            const int j = threadIdx.x;
            const float* f = (const float*)sred;    // row stride = 66 floats
            float v = 0.0f;
            #pragma unroll
            for (int w = 0; w < 8; ++w) v += f[w * 66 + j];

            int sample = n0 + j;
            float av = fabsf(v);
            if (sample < N) out[sample] = v; else av = 0.0f;
            #pragma unroll
            for (int o = 16; o > 0; o >>= 1)
                av = fmaxf(av, __shfl_xor_sync(0xFFFFFFFFu, av, o));
            if (lane == 0) atomicMax(&gPeakBits, __float_as_uint(av));
        }
        __syncthreads();                            // sred reuse safety
    }

    // ---- grid-wide barrier (all gridDim.x blocks are co-resident) ----------
    __threadfence();
    __syncthreads();
    if (threadIdx.x == 0) {
        int arrived = atomicAdd(&gSync, 1);
        if (arrived == gridDim.x - 1) {
            __threadfence();
            gFlag = 1;
        }
    }
    if (threadIdx.x == 0) { while (gFlag == 0) {} }
    __syncthreads();
    __threadfence();

    // ---- normalize phase ---------------------------------------------------
    float peak = __uint_as_float(gPeakBits) + 1e-8f;
    for (int idx = blockIdx.x * 256 + threadIdx.x; idx < N; idx += gridDim.x * 256)
        out[idx] = out[idx] / peak;
}

// ---------------------------------------------------------------------------
extern "C" void kernel_launch(void* const* d_in, const int* in_sizes, int n_in,
                              void* d_out, int out_size)
{
    const float* mu  = (const float*)d_in[0];
    const float* Dm  = (const float*)d_in[1];
    const float* T0m = (const float*)d_in[2];
    const float* Lyr = (const float*)d_in[3];
    const float* xr  = (const float*)d_in[4];
    const float* yr  = (const float*)d_in[5];
    int N  = out_size;                          // == num_samples
    int NC = (N + SCHUNK - 1) / SCHUNK;
    float* out = (float*)d_out;

    s1_kernel<<<GROUPS, GSZ>>>(mu, Dm, T0m, Lyr, xr, yr);
    plate_kernel<<<PBLK, 256>>>(out, N, NC);
}